// round 2
// baseline (speedup 1.0000x reference)
#include <cuda_runtime.h>
#include <math.h>

#define NI 80000
#define NU 20000
#define NN 100000
#define EE 1000000

// ---------------- scratch (static device globals; no allocs) ----------------
__device__ float g_x[NN * 64];
__device__ float g_xw[NN * 64];
__device__ float g_h[NN * 64];
__device__ float g_xhat[NN * 64];
__device__ float g_xcur[NN * 64];
__device__ int   g_cnt[NN];
__device__ int   g_deg[NN];
__device__ int   g_start[NN + 1];
__device__ int   g_cursor[NN];
__device__ int   g_csr[EE];
__device__ float g_dinv[NN];
__device__ int   g_bsum[128];
__device__ int   g_boff[128];

__device__ __forceinline__ float leaky(float v) { return v >= 0.f ? v : 0.01f * v; }

// ---------------- preprocessing ----------------
__global__ void k_zero() {
    int i = blockIdx.x * blockDim.x + threadIdx.x;
    if (i < NN) { g_cnt[i] = 0; g_deg[i] = 0; }
}

__global__ void k_hist(const int* __restrict__ src, const int* __restrict__ dst, int E) {
    int i = blockIdx.x * blockDim.x + threadIdx.x;
    if (i < E) {
        atomicAdd(&g_cnt[dst[i]], 1);
        atomicAdd(&g_deg[src[i]], 1);
    }
}

__global__ void k_scan1() {
    __shared__ int sd[1024];
    int t = threadIdx.x;
    int idx = blockIdx.x * 1024 + t;
    int v = (idx < NN) ? g_cnt[idx] : 0;
    sd[t] = v;
    __syncthreads();
    for (int off = 1; off < 1024; off <<= 1) {
        int add = (t >= off) ? sd[t - off] : 0;
        __syncthreads();
        sd[t] += add;
        __syncthreads();
    }
    if (idx < NN) g_start[idx + 1] = sd[t];
    if (t == 0) g_bsum[blockIdx.x] = sd[1023];
}

__global__ void k_scan2(int nb) {
    if (threadIdx.x == 0 && blockIdx.x == 0) {
        int run = 0;
        for (int b = 0; b < nb; b++) { g_boff[b] = run; run += g_bsum[b]; }
    }
}

__global__ void k_scan3() {
    int idx = blockIdx.x * 1024 + threadIdx.x;
    if (idx < NN) g_start[idx + 1] += g_boff[blockIdx.x];
    if (idx == 0) g_start[0] = 0;
}

__global__ void k_prep() {
    int i = blockIdx.x * blockDim.x + threadIdx.x;
    if (i < NN) {
        g_cursor[i] = g_start[i];
        int d = g_deg[i];
        g_dinv[i] = (d > 0) ? rsqrtf((float)d) : 0.f;
    }
}

__global__ void k_scatter(const int* __restrict__ src, const int* __restrict__ dst, int E) {
    int i = blockIdx.x * blockDim.x + threadIdx.x;
    if (i < E) {
        int d = dst[i];
        int p = atomicAdd(&g_cursor[d], 1);
        g_csr[p] = src[i];
    }
}

// ---------------- build x: items (copy + L2 normalize), warp per row ----------------
__global__ void k_items(const float* __restrict__ f) {
    int w = (blockIdx.x * blockDim.x + threadIdx.x) >> 5;
    int lane = threadIdx.x & 31;
    if (w >= NI) return;
    float2 v = *reinterpret_cast<const float2*>(f + (size_t)w * 64 + 2 * lane);
    float ss = v.x * v.x + v.y * v.y;
    ss += __shfl_xor_sync(0xffffffffu, ss, 16);
    ss += __shfl_xor_sync(0xffffffffu, ss, 8);
    ss += __shfl_xor_sync(0xffffffffu, ss, 4);
    ss += __shfl_xor_sync(0xffffffffu, ss, 2);
    ss += __shfl_xor_sync(0xffffffffu, ss, 1);
    float sc = 1.f / fmaxf(sqrtf(ss), 1e-12f);
    *reinterpret_cast<float2*>(g_x + (size_t)w * 64 + 2 * lane) = make_float2(v.x * sc, v.y * sc);
}

// ---------------- build x: users (tanh MLP + normalize), warp per row ----------------
__global__ void __launch_bounds__(256) k_users(const float* __restrict__ uf,
                                               const float* __restrict__ Wu,
                                               const float* __restrict__ bu) {
    __shared__ __align__(16) float ws[128 * 64];  // ws[k*64+c] = Wu[c*128+k]
    int tid = threadIdx.x;
    for (int i = tid; i < 8192; i += 256) {
        int c = i >> 7, k = i & 127;
        ws[k * 64 + c] = Wu[i];
    }
    __syncthreads();
    int lane = tid & 31, wp = tid >> 5;
    for (int u = blockIdx.x * 8 + wp; u < NU; u += gridDim.x * 8) {
        float4 my = *reinterpret_cast<const float4*>(uf + (size_t)u * 128 + lane * 4);
        float a0 = bu[2 * lane], a1 = bu[2 * lane + 1];
        for (int sl = 0; sl < 32; sl++) {
            float v0 = __shfl_sync(0xffffffffu, my.x, sl);
            float v1 = __shfl_sync(0xffffffffu, my.y, sl);
            float v2 = __shfl_sync(0xffffffffu, my.z, sl);
            float v3 = __shfl_sync(0xffffffffu, my.w, sl);
            int k0 = sl * 4;
            float2 w;
            w = *reinterpret_cast<const float2*>(&ws[(k0 + 0) * 64 + 2 * lane]);
            a0 = fmaf(v0, w.x, a0); a1 = fmaf(v0, w.y, a1);
            w = *reinterpret_cast<const float2*>(&ws[(k0 + 1) * 64 + 2 * lane]);
            a0 = fmaf(v1, w.x, a0); a1 = fmaf(v1, w.y, a1);
            w = *reinterpret_cast<const float2*>(&ws[(k0 + 2) * 64 + 2 * lane]);
            a0 = fmaf(v2, w.x, a0); a1 = fmaf(v2, w.y, a1);
            w = *reinterpret_cast<const float2*>(&ws[(k0 + 3) * 64 + 2 * lane]);
            a0 = fmaf(v3, w.x, a0); a1 = fmaf(v3, w.y, a1);
        }
        float t0 = tanhf(a0), t1 = tanhf(a1);
        float ss = t0 * t0 + t1 * t1;
        ss += __shfl_xor_sync(0xffffffffu, ss, 16);
        ss += __shfl_xor_sync(0xffffffffu, ss, 8);
        ss += __shfl_xor_sync(0xffffffffu, ss, 4);
        ss += __shfl_xor_sync(0xffffffffu, ss, 2);
        ss += __shfl_xor_sync(0xffffffffu, ss, 1);
        float sc = 1.f / fmaxf(sqrtf(ss), 1e-12f);
        *reinterpret_cast<float2*>(g_x + (size_t)(NI + u) * 64 + 2 * lane) =
            make_float2(t0 * sc, t1 * sc);
    }
}

// ---------------- generic 64x64 GEMM with epilogues ----------------
// mode 0: out = in@W'            (xw for GAT)
// mode 1: out = leaky(in@W' + bias) + add        (x_hat; add = id_embedding)
// mode 2: out = leaky(in@W' + bias + add); also out2[r*128+c] = out (add = x_hat)
__global__ void __launch_bounds__(128) k_gemm64(const float* __restrict__ in,
                                                const float* __restrict__ W, int transW,
                                                const float* __restrict__ bias, int mode,
                                                const float* __restrict__ add,
                                                float* __restrict__ outb,
                                                float* __restrict__ out2, int n) {
    __shared__ __align__(16) float ws[64 * 68];
    __shared__ float xs[64 * 65];
    int tid = threadIdx.x;
    for (int i = tid; i < 4096; i += 128) {
        int hi = i >> 6, lo = i & 63;
        int k = transW ? lo : hi;
        int c = transW ? hi : lo;
        ws[k * 68 + c] = W[i];
    }
    __syncthreads();
    int rg = tid >> 3;      // 0..15 (4 rows each)
    int cg = tid & 7;       // 0..7  (8 cols each)
    int c0 = cg * 8;
    int nt = (n + 63) >> 6;
    for (int tile = blockIdx.x; tile < nt; tile += gridDim.x) {
        int row0 = tile * 64;
        for (int i = tid; i < 4096; i += 128) {
            int r = i >> 6, k = i & 63;
            int gr = row0 + r;
            xs[r * 65 + k] = (gr < n) ? in[(size_t)gr * 64 + k] : 0.f;
        }
        __syncthreads();
        float acc[4][8];
#pragma unroll
        for (int rr = 0; rr < 4; rr++)
#pragma unroll
            for (int cc = 0; cc < 8; cc++) acc[rr][cc] = 0.f;
#pragma unroll 16
        for (int k = 0; k < 64; k++) {
            float4 w0 = *reinterpret_cast<const float4*>(&ws[k * 68 + c0]);
            float4 w1 = *reinterpret_cast<const float4*>(&ws[k * 68 + c0 + 4]);
#pragma unroll
            for (int rr = 0; rr < 4; rr++) {
                float a = xs[(rg * 4 + rr) * 65 + k];
                acc[rr][0] = fmaf(a, w0.x, acc[rr][0]);
                acc[rr][1] = fmaf(a, w0.y, acc[rr][1]);
                acc[rr][2] = fmaf(a, w0.z, acc[rr][2]);
                acc[rr][3] = fmaf(a, w0.w, acc[rr][3]);
                acc[rr][4] = fmaf(a, w1.x, acc[rr][4]);
                acc[rr][5] = fmaf(a, w1.y, acc[rr][5]);
                acc[rr][6] = fmaf(a, w1.z, acc[rr][6]);
                acc[rr][7] = fmaf(a, w1.w, acc[rr][7]);
            }
        }
#pragma unroll
        for (int rr = 0; rr < 4; rr++) {
            int r = row0 + rg * 4 + rr;
            if (r < n) {
                size_t base = (size_t)r * 64 + c0;
#pragma unroll
                for (int cc = 0; cc < 8; cc++) {
                    float v = acc[rr][cc];
                    int c = c0 + cc;
                    if (mode == 1) {
                        v = leaky(v + bias[c]) + add[base + cc];
                    } else if (mode == 2) {
                        v = leaky(v + bias[c] + add[base + cc]);
                    }
                    outb[base + cc] = v;
                    if (mode == 2) out2[(size_t)r * 128 + c] = v;
                }
            }
        }
        __syncthreads();
    }
}

// ---------------- GAT aggregation: warp per dst node, online softmax ----------------
__global__ void __launch_bounds__(256) k_agg() {
    int w = (blockIdx.x * blockDim.x + threadIdx.x) >> 5;
    int lane = threadIdx.x & 31;
    if (w >= NN) return;
    int s = g_start[w], e = g_start[w + 1];
    float2 xv = *reinterpret_cast<const float2*>(g_xw + (size_t)w * 64 + 2 * lane);
    float m = __int_as_float(0xff800000);  // -inf
    float z = 0.f;
    float2 acc = make_float2(0.f, 0.f);
    int cnt = e - s;
    int u_l = 0; float dv_l = 0.f;
    if (lane < cnt) { u_l = g_csr[s + lane]; dv_l = g_dinv[u_l]; }
    for (int i = 0; i < cnt; i++) {
        int j = i & 31;
        if (j == 0 && i > 0) {
            int idx = s + i + lane;
            u_l = (idx < e) ? g_csr[idx] : 0;
            dv_l = (idx < e) ? g_dinv[u_l] : 0.f;
        }
        int u = __shfl_sync(0xffffffffu, u_l, j);
        float dv = __shfl_sync(0xffffffffu, dv_l, j);
        float2 xu = *reinterpret_cast<const float2*>(g_xw + (size_t)u * 64 + 2 * lane);
        float p = fmaf(xv.x, xu.x, xv.y * xu.y);
        p += __shfl_xor_sync(0xffffffffu, p, 16);
        p += __shfl_xor_sync(0xffffffffu, p, 8);
        p += __shfl_xor_sync(0xffffffffu, p, 4);
        p += __shfl_xor_sync(0xffffffffu, p, 2);
        p += __shfl_xor_sync(0xffffffffu, p, 1);
        float inner = p;
        float gate = 1.f / (1.f + __expf(-inner * dv));
        float lg = inner * gate;
        float nm = fmaxf(m, lg);
        float scl = __expf(m - nm);   // exp(-inf)=0 on first edge
        float pe = __expf(lg - nm);
        z = z * scl + pe;
        acc.x = acc.x * scl + pe * xu.x;
        acc.y = acc.y * scl + pe * xu.y;
        m = nm;
    }
    float inv = 1.f / (z + 1e-16f);
    float rx = leaky(acc.x * inv);
    float ry = leaky(acc.y * inv);
    *reinterpret_cast<float2*>(g_h + (size_t)w * 64 + 2 * lane) = make_float2(rx, ry);
}

// ---------------- launch ----------------
extern "C" void kernel_launch(void* const* d_in, const int* in_sizes, int n_in,
                              void* d_out, int out_size) {
    const float* features = (const float*)d_in[0];
    const float* user_features = (const float*)d_in[1];
    const float* id_emb = (const float*)d_in[2];
    const float* user_mlp_w = (const float*)d_in[3];
    const float* user_mlp_b = (const float*)d_in[4];
    const float* gat1_w = (const float*)d_in[5];
    const float* lin1_w = (const float*)d_in[6];
    const float* lin1_b = (const float*)d_in[7];
    const float* g1_w = (const float*)d_in[8];
    const float* g1_b = (const float*)d_in[9];
    const float* gat2_w = (const float*)d_in[10];
    const float* lin2_w = (const float*)d_in[11];
    const float* lin2_b = (const float*)d_in[12];
    const float* g2_w = (const float*)d_in[13];
    const float* g2_b = (const float*)d_in[14];
    const int* edge_index = (const int*)d_in[15];
    float* out = (float*)d_out;

    int E = in_sizes[15] / 2;
    if (E > EE) E = EE;
    const int* src = edge_index;
    const int* dst = edge_index + E;

    float *p_x, *p_xw, *p_h, *p_xhat, *p_xcur;
    cudaGetSymbolAddress((void**)&p_x, g_x);
    cudaGetSymbolAddress((void**)&p_xw, g_xw);
    cudaGetSymbolAddress((void**)&p_h, g_h);
    cudaGetSymbolAddress((void**)&p_xhat, g_xhat);
    cudaGetSymbolAddress((void**)&p_xcur, g_xcur);

    int gn = (NN + 255) / 256;
    int ge = (E + 255) / 256;
    int nb = (NN + 1023) / 1024;

    // --- CSR + degree preprocessing ---
    k_zero<<<gn, 256>>>();
    k_hist<<<ge, 256>>>(src, dst, E);
    k_scan1<<<nb, 1024>>>();
    k_scan2<<<1, 32>>>(nb);
    k_scan3<<<nb, 1024>>>();
    k_prep<<<gn, 256>>>();
    k_scatter<<<ge, 256>>>(src, dst, E);

    // --- build normalized x ---
    k_items<<<NI / 8, 256>>>(features);
    k_users<<<592, 256>>>(user_features, user_mlp_w, user_mlp_b);

    const int GB = 888;  // persistent gemm blocks

    // --- hop 1 ---
    k_gemm64<<<GB, 128>>>(p_x, gat1_w, 0, nullptr, 0, nullptr, p_xw, nullptr, NN);
    k_agg<<<(NN + 7) / 8, 256>>>();
    k_gemm64<<<GB, 128>>>(p_x, lin1_w, 1, lin1_b, 1, id_emb, p_xhat, nullptr, NN);
    k_gemm64<<<GB, 128>>>(p_h, g1_w, 1, g1_b, 2, p_xhat, p_xcur, out, NN);

    // --- hop 2 ---
    k_gemm64<<<GB, 128>>>(p_xcur, gat2_w, 0, nullptr, 0, nullptr, p_xw, nullptr, NN);
    k_agg<<<(NN + 7) / 8, 256>>>();
    k_gemm64<<<GB, 128>>>(p_xcur, lin2_w, 1, lin2_b, 1, id_emb, p_xhat, nullptr, NN);
    k_gemm64<<<GB, 128>>>(p_h, g2_w, 1, g2_b, 2, p_xhat, p_x, out + 64, NN);
}

// round 5
// speedup vs baseline: 1.0832x; 1.0832x over previous
#include <cuda_runtime.h>
#include <math.h>

#define NI 80000
#define NU 20000
#define NN 100000
#define EE 1000000

// ---------------- scratch (static device globals; no allocs) ----------------
__device__ float g_x[NN * 64];
__device__ float g_xw[NN * 64];
__device__ float g_h[NN * 64];
__device__ float g_xhat[NN * 64];
__device__ float g_xcur[NN * 64];
__device__ int   g_cnt[NN];
__device__ int   g_deg[NN];
__device__ int   g_start[NN + 1];
__device__ int   g_cursor[NN];
__device__ int   g_csr[EE];
__device__ float g_dinv[NN];
__device__ int   g_bsum[128];
__device__ int   g_boff[128];

__device__ __forceinline__ float leaky(float v) { return v >= 0.f ? v : 0.01f * v; }

__device__ __forceinline__ unsigned long long packdup(float a) {
    unsigned long long r;
    asm("mov.b64 %0, {%1, %1};" : "=l"(r) : "f"(a));
    return r;
}
__device__ __forceinline__ void ffma2(unsigned long long& d, unsigned long long a,
                                      unsigned long long b) {
    asm("fma.rn.f32x2 %0, %1, %2, %0;" : "+l"(d) : "l"(a), "l"(b));
}
__device__ __forceinline__ float2 unpack2(unsigned long long v) {
    float2 f;
    asm("mov.b64 {%0, %1}, %2;" : "=f"(f.x), "=f"(f.y) : "l"(v));
    return f;
}

// ---------------- preprocessing ----------------
__global__ void k_zero() {
    int i = blockIdx.x * blockDim.x + threadIdx.x;
    if (i < NN) { g_cnt[i] = 0; g_deg[i] = 0; }
}

__global__ void k_hist(const int* __restrict__ src, const int* __restrict__ dst, int E) {
    int i = blockIdx.x * blockDim.x + threadIdx.x;
    if (i < E) {
        atomicAdd(&g_cnt[dst[i]], 1);
        atomicAdd(&g_deg[src[i]], 1);
    }
}

__global__ void k_scan1() {
    __shared__ int sd[1024];
    int t = threadIdx.x;
    int idx = blockIdx.x * 1024 + t;
    int v = (idx < NN) ? g_cnt[idx] : 0;
    sd[t] = v;
    __syncthreads();
    for (int off = 1; off < 1024; off <<= 1) {
        int add = (t >= off) ? sd[t - off] : 0;
        __syncthreads();
        sd[t] += add;
        __syncthreads();
    }
    if (idx < NN) g_start[idx + 1] = sd[t];
    if (t == 0) g_bsum[blockIdx.x] = sd[1023];
}

__global__ void k_scan2p(int nb) {
    __shared__ int s[128];
    int t = threadIdx.x;
    int v = (t < nb) ? g_bsum[t] : 0;
    s[t] = v;
    __syncthreads();
    for (int off = 1; off < 128; off <<= 1) {
        int add = (t >= off) ? s[t - off] : 0;
        __syncthreads();
        s[t] += add;
        __syncthreads();
    }
    if (t < nb) g_boff[t] = s[t] - v;  // exclusive
}

// scan finalize + prep merged
__global__ void k_scan3() {
    int idx = blockIdx.x * 1024 + threadIdx.x;
    if (idx < NN) {
        int v = g_start[idx + 1] + g_boff[blockIdx.x];
        g_start[idx + 1] = v;
        if (idx + 1 < NN) g_cursor[idx + 1] = v;
        int d = g_deg[idx];
        g_dinv[idx] = (d > 0) ? rsqrtf((float)d) : 0.f;
    }
    if (idx == 0) { g_start[0] = 0; g_cursor[0] = 0; }
}

__global__ void k_scatter(const int* __restrict__ src, const int* __restrict__ dst, int E) {
    int i = blockIdx.x * blockDim.x + threadIdx.x;
    if (i < E) {
        int d = dst[i];
        int p = atomicAdd(&g_cursor[d], 1);
        g_csr[p] = src[i];
    }
}

// ---------------- build x: items (copy + L2 normalize), warp per row ----------------
__global__ void k_items(const float* __restrict__ f) {
    int w = (blockIdx.x * blockDim.x + threadIdx.x) >> 5;
    int lane = threadIdx.x & 31;
    if (w >= NI) return;
    float2 v = *reinterpret_cast<const float2*>(f + (size_t)w * 64 + 2 * lane);
    float ss = v.x * v.x + v.y * v.y;
    ss += __shfl_xor_sync(0xffffffffu, ss, 16);
    ss += __shfl_xor_sync(0xffffffffu, ss, 8);
    ss += __shfl_xor_sync(0xffffffffu, ss, 4);
    ss += __shfl_xor_sync(0xffffffffu, ss, 2);
    ss += __shfl_xor_sync(0xffffffffu, ss, 1);
    float sc = 1.f / fmaxf(sqrtf(ss), 1e-12f);
    *reinterpret_cast<float2*>(g_x + (size_t)w * 64 + 2 * lane) = make_float2(v.x * sc, v.y * sc);
}

// ---------------- build x: users (tanh MLP + normalize), warp per row ----------------
__global__ void __launch_bounds__(256) k_users(const float* __restrict__ uf,
                                               const float* __restrict__ Wu,
                                               const float* __restrict__ bu) {
    __shared__ __align__(16) float ws[128 * 64];  // ws[k*64+c] = Wu[c*128+k]
    int tid = threadIdx.x;
    for (int i = tid; i < 8192; i += 256) {
        int c = i >> 7, k = i & 127;
        ws[k * 64 + c] = Wu[i];
    }
    __syncthreads();
    int lane = tid & 31, wp = tid >> 5;
    for (int u = blockIdx.x * 8 + wp; u < NU; u += gridDim.x * 8) {
        float4 my = *reinterpret_cast<const float4*>(uf + (size_t)u * 128 + lane * 4);
        float a0 = bu[2 * lane], a1 = bu[2 * lane + 1];
        for (int sl = 0; sl < 32; sl++) {
            float v0 = __shfl_sync(0xffffffffu, my.x, sl);
            float v1 = __shfl_sync(0xffffffffu, my.y, sl);
            float v2 = __shfl_sync(0xffffffffu, my.z, sl);
            float v3 = __shfl_sync(0xffffffffu, my.w, sl);
            int k0 = sl * 4;
            float2 w;
            w = *reinterpret_cast<const float2*>(&ws[(k0 + 0) * 64 + 2 * lane]);
            a0 = fmaf(v0, w.x, a0); a1 = fmaf(v0, w.y, a1);
            w = *reinterpret_cast<const float2*>(&ws[(k0 + 1) * 64 + 2 * lane]);
            a0 = fmaf(v1, w.x, a0); a1 = fmaf(v1, w.y, a1);
            w = *reinterpret_cast<const float2*>(&ws[(k0 + 2) * 64 + 2 * lane]);
            a0 = fmaf(v2, w.x, a0); a1 = fmaf(v2, w.y, a1);
            w = *reinterpret_cast<const float2*>(&ws[(k0 + 3) * 64 + 2 * lane]);
            a0 = fmaf(v3, w.x, a0); a1 = fmaf(v3, w.y, a1);
        }
        float t0 = tanhf(a0), t1 = tanhf(a1);
        float ss = t0 * t0 + t1 * t1;
        ss += __shfl_xor_sync(0xffffffffu, ss, 16);
        ss += __shfl_xor_sync(0xffffffffu, ss, 8);
        ss += __shfl_xor_sync(0xffffffffu, ss, 4);
        ss += __shfl_xor_sync(0xffffffffu, ss, 2);
        ss += __shfl_xor_sync(0xffffffffu, ss, 1);
        float sc = 1.f / fmaxf(sqrtf(ss), 1e-12f);
        *reinterpret_cast<float2*>(g_x + (size_t)(NI + u) * 64 + 2 * lane) =
            make_float2(t0 * sc, t1 * sc);
    }
}

// ---------------- fused dual GEMM: xw = in@Wg ; xhat = leaky(in@Wl' + b) + id ----------
__global__ void __launch_bounds__(128) k_dual(const float* __restrict__ in,
                                              const float* __restrict__ Wg,
                                              const float* __restrict__ Wl,
                                              const float* __restrict__ bias,
                                              const float* __restrict__ idw,
                                              float* __restrict__ xw,
                                              float* __restrict__ xhat, int n) {
    __shared__ __align__(16) float ws1[4096];
    __shared__ __align__(16) float ws2[4096];
    __shared__ __align__(16) float xs[4096];
    int tid = threadIdx.x;
    for (int i = tid; i < 4096; i += 128) {
        int k = i >> 6, c = i & 63;
        ws1[i] = Wg[i];           // direct [k][c]
        ws2[i] = Wl[c * 64 + k];  // transposed read, linear smem write
    }
    __syncthreads();
    int rg = tid >> 3;   // 0..15 -> 4 rows each
    int cg = tid & 7;    // 0..7  -> 8 cols each
    int c0 = cg * 8;
    int swz = (rg & 7) * 8;  // warp spans rg 0..3 -> distinct banks
    float4 b0 = *(const float4*)(bias + c0);
    float4 b1 = *(const float4*)(bias + c0 + 4);
    int nt = (n + 63) >> 6;
    for (int tile = blockIdx.x; tile < nt; tile += gridDim.x) {
        int row0 = tile * 64;
        for (int i = tid * 4; i < 4096; i += 512) {
            int r = i >> 6, k = i & 63;
            int sw = ((r >> 2) & 7) * 8;
            int gr = row0 + r;
            float4 v = (gr < n) ? *(const float4*)(in + (size_t)gr * 64 + k)
                                : make_float4(0.f, 0.f, 0.f, 0.f);
            *(float4*)&xs[r * 64 + (k ^ sw)] = v;
        }
        __syncthreads();
        unsigned long long aG[4][4], aL[4][4];
#pragma unroll
        for (int rr = 0; rr < 4; rr++)
#pragma unroll
            for (int p = 0; p < 4; p++) { aG[rr][p] = 0ull; aL[rr][p] = 0ull; }
#pragma unroll 2
        for (int kb = 0; kb < 64; kb += 4) {
            float4 a4[4];
#pragma unroll
            for (int rr = 0; rr < 4; rr++)
                a4[rr] = *(const float4*)&xs[(rg * 4 + rr) * 64 + (kb ^ swz)];
#pragma unroll
            for (int j = 0; j < 4; j++) {
                int k = kb + j;
                ulonglong2 gA = *(const ulonglong2*)&ws1[k * 64 + c0];
                ulonglong2 gB = *(const ulonglong2*)&ws1[k * 64 + c0 + 4];
                ulonglong2 lA = *(const ulonglong2*)&ws2[k * 64 + c0];
                ulonglong2 lB = *(const ulonglong2*)&ws2[k * 64 + c0 + 4];
#pragma unroll
                for (int rr = 0; rr < 4; rr++) {
                    float a = (j == 0) ? a4[rr].x : (j == 1) ? a4[rr].y
                              : (j == 2) ? a4[rr].z : a4[rr].w;
                    unsigned long long aa = packdup(a);
                    ffma2(aG[rr][0], aa, gA.x); ffma2(aG[rr][1], aa, gA.y);
                    ffma2(aG[rr][2], aa, gB.x); ffma2(aG[rr][3], aa, gB.y);
                    ffma2(aL[rr][0], aa, lA.x); ffma2(aL[rr][1], aa, lA.y);
                    ffma2(aL[rr][2], aa, lB.x); ffma2(aL[rr][3], aa, lB.y);
                }
            }
        }
#pragma unroll
        for (int rr = 0; rr < 4; rr++) {
            int r = row0 + rg * 4 + rr;
            if (r < n) {
                size_t base = (size_t)r * 64 + c0;
                float2 v0 = unpack2(aG[rr][0]), v1 = unpack2(aG[rr][1]);
                float2 v2 = unpack2(aG[rr][2]), v3 = unpack2(aG[rr][3]);
                *(float4*)(xw + base) = make_float4(v0.x, v0.y, v1.x, v1.y);
                *(float4*)(xw + base + 4) = make_float4(v2.x, v2.y, v3.x, v3.y);
                float2 u0 = unpack2(aL[rr][0]), u1 = unpack2(aL[rr][1]);
                float2 u2 = unpack2(aL[rr][2]), u3 = unpack2(aL[rr][3]);
                float4 i0 = *(const float4*)(idw + base);
                float4 i1 = *(const float4*)(idw + base + 4);
                float4 o0 = make_float4(leaky(u0.x + b0.x) + i0.x,
                                        leaky(u0.y + b0.y) + i0.y,
                                        leaky(u1.x + b0.z) + i0.z,
                                        leaky(u1.y + b0.w) + i0.w);
                float4 o1 = make_float4(leaky(u2.x + b1.x) + i1.x,
                                        leaky(u2.y + b1.y) + i1.y,
                                        leaky(u3.x + b1.z) + i1.z,
                                        leaky(u3.y + b1.w) + i1.w);
                *(float4*)(xhat + base) = o0;
                *(float4*)(xhat + base + 4) = o1;
            }
        }
        __syncthreads();
    }
}

// ---------------- final GEMM: v = leaky(h@W' + b + xhat); write outb & out2 ----------
__global__ void __launch_bounds__(128) k_final(const float* __restrict__ in,
                                               const float* __restrict__ W,
                                               const float* __restrict__ bias,
                                               const float* __restrict__ add,
                                               float* __restrict__ outb,
                                               float* __restrict__ out2, int n) {
    __shared__ __align__(16) float ws[4096];
    __shared__ __align__(16) float xs[4096];
    int tid = threadIdx.x;
    for (int i = tid; i < 4096; i += 128) {
        int k = i >> 6, c = i & 63;
        ws[i] = W[c * 64 + k];  // transposed
    }
    __syncthreads();
    int rg = tid >> 3, cg = tid & 7;
    int c0 = cg * 8;
    int swz = (rg & 7) * 8;
    float4 b0 = *(const float4*)(bias + c0);
    float4 b1 = *(const float4*)(bias + c0 + 4);
    int nt = (n + 63) >> 6;
    for (int tile = blockIdx.x; tile < nt; tile += gridDim.x) {
        int row0 = tile * 64;
        for (int i = tid * 4; i < 4096; i += 512) {
            int r = i >> 6, k = i & 63;
            int sw = ((r >> 2) & 7) * 8;
            int gr = row0 + r;
            float4 v = (gr < n) ? *(const float4*)(in + (size_t)gr * 64 + k)
                                : make_float4(0.f, 0.f, 0.f, 0.f);
            *(float4*)&xs[r * 64 + (k ^ sw)] = v;
        }
        __syncthreads();
        unsigned long long aA[4][4];
#pragma unroll
        for (int rr = 0; rr < 4; rr++)
#pragma unroll
            for (int p = 0; p < 4; p++) aA[rr][p] = 0ull;
#pragma unroll 4
        for (int kb = 0; kb < 64; kb += 4) {
            float4 a4[4];
#pragma unroll
            for (int rr = 0; rr < 4; rr++)
                a4[rr] = *(const float4*)&xs[(rg * 4 + rr) * 64 + (kb ^ swz)];
#pragma unroll
            for (int j = 0; j < 4; j++) {
                int k = kb + j;
                ulonglong2 wA = *(const ulonglong2*)&ws[k * 64 + c0];
                ulonglong2 wB = *(const ulonglong2*)&ws[k * 64 + c0 + 4];
#pragma unroll
                for (int rr = 0; rr < 4; rr++) {
                    float a = (j == 0) ? a4[rr].x : (j == 1) ? a4[rr].y
                              : (j == 2) ? a4[rr].z : a4[rr].w;
                    unsigned long long aa = packdup(a);
                    ffma2(aA[rr][0], aa, wA.x); ffma2(aA[rr][1], aa, wA.y);
                    ffma2(aA[rr][2], aa, wB.x); ffma2(aA[rr][3], aa, wB.y);
                }
            }
        }
#pragma unroll
        for (int rr = 0; rr < 4; rr++) {
            int r = row0 + rg * 4 + rr;
            if (r < n) {
                size_t base = (size_t)r * 64 + c0;
                float2 u0 = unpack2(aA[rr][0]), u1 = unpack2(aA[rr][1]);
                float2 u2 = unpack2(aA[rr][2]), u3 = unpack2(aA[rr][3]);
                float4 h0 = *(const float4*)(add + base);
                float4 h1 = *(const float4*)(add + base + 4);
                float4 o0 = make_float4(leaky(u0.x + b0.x + h0.x),
                                        leaky(u0.y + b0.y + h0.y),
                                        leaky(u1.x + b0.z + h0.z),
                                        leaky(u1.y + b0.w + h0.w));
                float4 o1 = make_float4(leaky(u2.x + b1.x + h1.x),
                                        leaky(u2.y + b1.y + h1.y),
                                        leaky(u3.x + b1.z + h1.z),
                                        leaky(u3.y + b1.w + h1.w));
                *(float4*)(outb + base) = o0;
                *(float4*)(outb + base + 4) = o1;
                *(float4*)(out2 + (size_t)r * 128 + c0) = o0;
                *(float4*)(out2 + (size_t)r * 128 + c0 + 4) = o1;
            }
        }
        __syncthreads();
    }
}

// ---------------- GAT aggregation: warp per dst node, 2-edge online softmax --------
__global__ void __launch_bounds__(256) k_agg() {
    int w = (blockIdx.x * blockDim.x + threadIdx.x) >> 5;
    int lane = threadIdx.x & 31;
    if (w >= NN) return;
    int s = g_start[w], e = g_start[w + 1];
    int cnt = e - s;
    float2 xv = *reinterpret_cast<const float2*>(g_xw + (size_t)w * 64 + 2 * lane);
    const float NEGINF = __int_as_float(0xff800000);
    float m = NEGINF, z = 0.f;
    float2 acc = make_float2(0.f, 0.f);
    int u_l = 0; float dv_l = 0.f;
    if (lane < cnt) { u_l = g_csr[s + lane]; dv_l = g_dinv[u_l]; }
    for (int i = 0; i < cnt; i += 2) {
        int j = i & 31;
        if (j == 0 && i > 0) {
            int idx = s + i + lane;
            u_l = (idx < e) ? g_csr[idx] : 0;
            dv_l = (idx < e) ? g_dinv[u_l] : 0.f;
        }
        bool has2 = (i + 1) < cnt;
        int u0 = __shfl_sync(0xffffffffu, u_l, j);
        int u1 = __shfl_sync(0xffffffffu, u_l, j + 1);
        float dv0 = __shfl_sync(0xffffffffu, dv_l, j);
        float dv1 = __shfl_sync(0xffffffffu, dv_l, j + 1);
        float2 xu0 = *reinterpret_cast<const float2*>(g_xw + (size_t)u0 * 64 + 2 * lane);
        float2 xu1 = *reinterpret_cast<const float2*>(g_xw + (size_t)u1 * 64 + 2 * lane);
        float p0 = fmaf(xv.x, xu0.x, xv.y * xu0.y);
        float p1 = fmaf(xv.x, xu1.x, xv.y * xu1.y);
#pragma unroll
        for (int o = 16; o; o >>= 1) {
            p0 += __shfl_xor_sync(0xffffffffu, p0, o);
            p1 += __shfl_xor_sync(0xffffffffu, p1, o);
        }
        float lg0 = p0 * (1.f / (1.f + __expf(-p0 * dv0)));
        float lg1 = has2 ? p1 * (1.f / (1.f + __expf(-p1 * dv1))) : NEGINF;
        float nm = fmaxf(m, fmaxf(lg0, lg1));
        float scl = __expf(m - nm);  // exp(-inf)=0 on first pair
        float pe0 = __expf(lg0 - nm);
        float pe1 = has2 ? __expf(lg1 - nm) : 0.f;
        z = z * scl + pe0 + pe1;
        acc.x = acc.x * scl + pe0 * xu0.x + pe1 * xu1.x;
        acc.y = acc.y * scl + pe0 * xu0.y + pe1 * xu1.y;
        m = nm;
    }
    float inv = 1.f / (z + 1e-16f);
    float rx = leaky(acc.x * inv);
    float ry = leaky(acc.y * inv);
    *reinterpret_cast<float2*>(g_h + (size_t)w * 64 + 2 * lane) = make_float2(rx, ry);
}

// ---------------- launch ----------------
extern "C" void kernel_launch(void* const* d_in, const int* in_sizes, int n_in,
                              void* d_out, int out_size) {
    const float* features = (const float*)d_in[0];
    const float* user_features = (const float*)d_in[1];
    const float* id_emb = (const float*)d_in[2];
    const float* user_mlp_w = (const float*)d_in[3];
    const float* user_mlp_b = (const float*)d_in[4];
    const float* gat1_w = (const float*)d_in[5];
    const float* lin1_w = (const float*)d_in[6];
    const float* lin1_b = (const float*)d_in[7];
    const float* g1_w = (const float*)d_in[8];
    const float* g1_b = (const float*)d_in[9];
    const float* gat2_w = (const float*)d_in[10];
    const float* lin2_w = (const float*)d_in[11];
    const float* lin2_b = (const float*)d_in[12];
    const float* g2_w = (const float*)d_in[13];
    const float* g2_b = (const float*)d_in[14];
    const int* edge_index = (const int*)d_in[15];
    float* out = (float*)d_out;

    int E = in_sizes[15] / 2;
    if (E > EE) E = EE;
    const int* src = edge_index;
    const int* dst = edge_index + E;

    float *p_x, *p_xw, *p_h, *p_xhat, *p_xcur;
    cudaGetSymbolAddress((void**)&p_x, g_x);
    cudaGetSymbolAddress((void**)&p_xw, g_xw);
    cudaGetSymbolAddress((void**)&p_h, g_h);
    cudaGetSymbolAddress((void**)&p_xhat, g_xhat);
    cudaGetSymbolAddress((void**)&p_xcur, g_xcur);

    int gn = (NN + 255) / 256;
    int ge = (E + 255) / 256;
    int nb = (NN + 1023) / 1024;

    // --- CSR + degree preprocessing ---
    k_zero<<<gn, 256>>>();
    k_hist<<<ge, 256>>>(src, dst, E);
    k_scan1<<<nb, 1024>>>();
    k_scan2p<<<1, 128>>>(nb);
    k_scan3<<<nb, 1024>>>();
    k_scatter<<<ge, 256>>>(src, dst, E);

    // --- build normalized x ---
    k_items<<<NI / 8, 256>>>(features);
    k_users<<<592, 256>>>(user_features, user_mlp_w, user_mlp_b);

    const int GB = 592;  // persistent gemm blocks

    // --- hop 1 ---
    k_dual<<<GB, 128>>>(p_x, gat1_w, lin1_w, lin1_b, id_emb, p_xw, p_xhat, NN);
    k_agg<<<(NN + 7) / 8, 256>>>();
    k_final<<<GB, 128>>>(p_h, g1_w, g1_b, p_xhat, p_xcur, out, NN);

    // --- hop 2 ---
    k_dual<<<GB, 128>>>(p_xcur, gat2_w, lin2_w, lin2_b, id_emb, p_xw, p_xhat, NN);
    k_agg<<<(NN + 7) / 8, 256>>>();
    k_final<<<GB, 128>>>(p_h, g2_w, g2_b, p_xhat, p_x, out + 64, NN);
}